// round 1
// baseline (speedup 1.0000x reference)
#include <cuda_runtime.h>
#include <math.h>

// Problem constants
constexpr int TT  = 2048;   // tokens = B*S
constexpr int HH  = 2048;   // hidden
constexpr int II  = 8192;   // shared intermediate
constexpr int EE  = 32;     // experts
constexpr int KT  = 4;      // top-k
constexpr int MI  = 1408;   // moe intermediate
constexpr int CAP = 2048;   // per-expert token capacity (worst case)

// Scratch (device globals: allocation-free per harness rules)
__device__ float g_h1[(size_t)TT * II];            // shared-expert hidden (silu'ed)  64 MB
__device__ float g_act[(size_t)EE * CAP * MI];     // expert up activations (silu'ed) 369 MB
__device__ int   g_cnt[EE];
__device__ int   g_tok[EE * CAP];
__device__ float g_wt[EE * CAP];

__device__ __forceinline__ float silu_f(float v) { return v / (1.0f + expf(-v)); }

__global__ void reset_kernel() {
    if (threadIdx.x < EE) g_cnt[threadIdx.x] = 0;
}

// Router logits: one warp per token, lane = expert column.
__global__ void router_kernel(const float* __restrict__ x, const float* __restrict__ gw,
                              float* __restrict__ logits) {
    int t = blockIdx.x * 8 + threadIdx.y;
    int lane = threadIdx.x;
    const float* xr = x + (size_t)t * HH;
    float acc = 0.f;
    for (int h = 0; h < HH; h += 32) {
        float xv = xr[h + lane];
        #pragma unroll
        for (int j = 0; j < 32; j++) {
            float xb = __shfl_sync(0xffffffffu, xv, j);
            acc = fmaf(xb, gw[(size_t)(h + j) * EE + lane], acc);
        }
    }
    logits[(size_t)t * EE + lane] = acc;
}

// Top-4 + softmax per token (warp per token), scatter into per-expert lists.
__global__ void topk_kernel(const float* __restrict__ logits) {
    int t = blockIdx.x * 8 + threadIdx.y;
    int lane = threadIdx.x;
    float cur = logits[(size_t)t * EE + lane];
    float vals[KT]; int idxs[KT];
    #pragma unroll
    for (int k = 0; k < KT; k++) {
        float bv = cur; int bi = lane;
        #pragma unroll
        for (int off = 16; off; off >>= 1) {
            float ov = __shfl_xor_sync(0xffffffffu, bv, off);
            int   oi = __shfl_xor_sync(0xffffffffu, bi, off);
            if (ov > bv || (ov == bv && oi < bi)) { bv = ov; bi = oi; }
        }
        vals[k] = bv; idxs[k] = bi;
        if (lane == bi) cur = -3.402823466e38f;
    }
    if (lane == 0) {
        float m = vals[0], s = 0.f, e[KT];
        #pragma unroll
        for (int k = 0; k < KT; k++) { e[k] = expf(vals[k] - m); s += e[k]; }
        float inv = 1.f / s;
        #pragma unroll
        for (int k = 0; k < KT; k++) {
            int ex = idxs[k];
            int slot = atomicAdd(&g_cnt[ex], 1);
            g_tok[ex * CAP + slot] = t;
            g_wt[ex * CAP + slot]  = e[k] * inv;
        }
    }
}

// Generic 128x128 fp32 GEMM, BK=8, 256 threads, 8x8 microtile, double-buffered smem.
// MODE 0: C=g_h1, silu(x @ ws1)               [T,H]x[H,I]
// MODE 1: C=out,  g_h1 @ ws2 (plain store)    [T,I]x[I,H]
// MODE 2: C=g_act, silu(gather(x) @ w1[e])    per-expert, A row gather via g_tok
// MODE 3: atomicAdd(out[token], w * (g_act[e] @ w2[e]))
template <int MODE>
__global__ __launch_bounds__(256)
void gemm128(const float* __restrict__ Ain, const float* __restrict__ Bin,
             float* __restrict__ Cout, int Mrows, int N, int Kd) {
    int e = 0, rows = Mrows;
    const float* A = Ain;
    const float* B = Bin;
    const int*   tokl = nullptr;
    const float* wtl  = nullptr;
    if (MODE == 2 || MODE == 3) {
        e = blockIdx.z;
        rows = g_cnt[e];
        if ((int)(blockIdx.y * 128) >= rows) return;   // early-exit empty row tiles
        tokl = g_tok + e * CAP;
        wtl  = g_wt  + e * CAP;
        if (MODE == 2) { B = Bin + (size_t)e * HH * MI; }
        else           { A = g_act + (size_t)e * CAP * MI; B = Bin + (size_t)e * MI * HH; }
    }
    if (MODE == 1) A = g_h1;

    __shared__ float As[2][8][128];
    __shared__ float Bs[2][8][128];

    int tid  = threadIdx.x;
    int tx   = tid & 15, ty = tid >> 4;
    int ar   = tid >> 1, ac = (tid & 1) * 4;
    int brow = tid >> 5, bcol = (tid & 31) * 4;
    int row0 = blockIdx.y * 128, col0 = blockIdx.x * 128;

    const float* aRow;
    if (MODE == 2) {
        int gr = row0 + ar;
        int tokr = (gr < rows) ? tokl[gr] : 0;   // safe fallback row
        aRow = A + (size_t)tokr * Kd + ac;
    } else {
        aRow = A + (size_t)(row0 + ar) * Kd + ac; // MODE3: rows<CAP but memory valid up to CAP
    }
    const float* bRow = B + (size_t)brow * N + col0 + bcol;

    float acc[8][8];
    #pragma unroll
    for (int i = 0; i < 8; i++)
        #pragma unroll
        for (int j = 0; j < 8; j++) acc[i][j] = 0.f;

    {
        float4 a0 = *(const float4*)aRow;
        float4 b0 = *(const float4*)bRow;
        As[0][ac + 0][ar] = a0.x; As[0][ac + 1][ar] = a0.y;
        As[0][ac + 2][ar] = a0.z; As[0][ac + 3][ar] = a0.w;
        *(float4*)&Bs[0][brow][bcol] = b0;
    }
    __syncthreads();

    int buf = 0;
    for (int k0 = 8; k0 <= Kd; k0 += 8) {
        float4 aN, bN;
        bool more = (k0 < Kd);
        if (more) {
            aN = *(const float4*)(aRow + k0);
            bN = *(const float4*)(bRow + (size_t)k0 * N);
        }
        #pragma unroll
        for (int kk = 0; kk < 8; kk++) {
            float4 a01 = *(const float4*)&As[buf][kk][ty * 8];
            float4 a23 = *(const float4*)&As[buf][kk][ty * 8 + 4];
            float4 b01 = *(const float4*)&Bs[buf][kk][tx * 8];
            float4 b23 = *(const float4*)&Bs[buf][kk][tx * 8 + 4];
            float aa[8] = {a01.x, a01.y, a01.z, a01.w, a23.x, a23.y, a23.z, a23.w};
            float bb[8] = {b01.x, b01.y, b01.z, b01.w, b23.x, b23.y, b23.z, b23.w};
            #pragma unroll
            for (int i = 0; i < 8; i++)
                #pragma unroll
                for (int j = 0; j < 8; j++)
                    acc[i][j] = fmaf(aa[i], bb[j], acc[i][j]);
        }
        if (more) {
            int nb = buf ^ 1;
            As[nb][ac + 0][ar] = aN.x; As[nb][ac + 1][ar] = aN.y;
            As[nb][ac + 2][ar] = aN.z; As[nb][ac + 3][ar] = aN.w;
            *(float4*)&Bs[nb][brow][bcol] = bN;
            __syncthreads();
            buf = nb;
        }
    }

    #pragma unroll
    for (int i = 0; i < 8; i++) {
        int r = row0 + ty * 8 + i;
        if (r >= rows) continue;
        int c = col0 + tx * 8;
        if (MODE == 0) {
            float* cp = g_h1 + (size_t)r * II + c;
            #pragma unroll
            for (int j = 0; j < 8; j++) cp[j] = silu_f(acc[i][j]);
        } else if (MODE == 1) {
            float* cp = Cout + (size_t)r * HH + c;
            #pragma unroll
            for (int j = 0; j < 8; j++) cp[j] = acc[i][j];
        } else if (MODE == 2) {
            float* cp = g_act + ((size_t)e * CAP + r) * MI + c;
            #pragma unroll
            for (int j = 0; j < 8; j++) cp[j] = silu_f(acc[i][j]);
        } else {
            int tokn = tokl[r];
            float w  = wtl[r];
            float* cp = Cout + (size_t)tokn * HH + c;
            #pragma unroll
            for (int j = 0; j < 8; j++) atomicAdd(&cp[j], acc[i][j] * w);
        }
    }
}

extern "C" void kernel_launch(void* const* d_in, const int* in_sizes, int n_in,
                              void* d_out, int out_size) {
    (void)in_sizes; (void)n_in; (void)out_size;
    const float* x   = (const float*)d_in[0];   // [T, H]
    const float* gw  = (const float*)d_in[1];   // [H, E]
    const float* w1  = (const float*)d_in[2];   // [E, H, M]
    const float* w2  = (const float*)d_in[3];   // [E, M, H]
    const float* ws1 = (const float*)d_in[4];   // [H, I]
    const float* ws2 = (const float*)d_in[5];   // [I, H]
    float* out    = (float*)d_out;              // [T, H] then [T, E] logits
    float* logits = out + (size_t)TT * HH;

    reset_kernel<<<1, 32>>>();
    router_kernel<<<TT / 8, dim3(32, 8)>>>(x, gw, logits);
    topk_kernel<<<TT / 8, dim3(32, 8)>>>(logits);

    // expert up: silu(gather(x) @ w1[e]) -> g_act   (runs independent of shared path)
    gemm128<2><<<dim3(MI / 128, CAP / 128, EE), 256>>>(x, w1, nullptr, CAP, MI, HH);
    // shared expert: h1 = silu(x @ ws1); out = h1 @ ws2 (plain store initializes out)
    gemm128<0><<<dim3(II / 128, TT / 128), 256>>>(x, ws1, nullptr, TT, II, HH);
    gemm128<1><<<dim3(HH / 128, TT / 128), 256>>>(nullptr, ws2, out, TT, HH, II);
    // expert down: out += w * (g_act[e] @ w2[e])  (atomic, after MODE1 store)
    gemm128<3><<<dim3(HH / 128, CAP / 128, EE), 256>>>(nullptr, w2, out, CAP, HH, MI);
}

// round 4
// speedup vs baseline: 2.0974x; 2.0974x over previous
#include <cuda_runtime.h>
#include <math.h>

// Problem constants
constexpr int TT  = 2048;   // tokens = B*S
constexpr int HH  = 2048;   // hidden
constexpr int II  = 8192;   // shared intermediate
constexpr int EE  = 32;     // experts
constexpr int KT  = 4;      // top-k
constexpr int MI  = 1408;   // moe intermediate
constexpr int CAP = 2048;   // per-expert token capacity (worst case)

// Scratch (device globals: allocation-free per harness rules)
__device__ float g_h1[(size_t)TT * II];            // shared-expert hidden (silu'ed)
__device__ float g_act[(size_t)EE * CAP * MI];     // expert up activations (silu'ed)
__device__ int   g_cnt[EE];
__device__ int   g_tok[EE * CAP];
__device__ float g_wt[EE * CAP];

__device__ __forceinline__ float silu_f(float v) { return v / (1.0f + expf(-v)); }
__device__ __forceinline__ float f2tf(float v) {
    unsigned r;
    asm("cvt.rna.tf32.f32 %0, %1;" : "=r"(r) : "f"(v));
    return __uint_as_float(r);
}

__global__ void reset_kernel() {
    if (threadIdx.x < EE) g_cnt[threadIdx.x] = 0;
}

// Router logits: one warp per token, lane = expert column. Exact fp32 (part of output).
__global__ void router_kernel(const float* __restrict__ x, const float* __restrict__ gw,
                              float* __restrict__ logits) {
    int t = blockIdx.x * 8 + threadIdx.y;
    int lane = threadIdx.x;
    const float* xr = x + (size_t)t * HH;
    float acc = 0.f;
    for (int h = 0; h < HH; h += 32) {
        float xv = xr[h + lane];
        #pragma unroll
        for (int j = 0; j < 32; j++) {
            float xb = __shfl_sync(0xffffffffu, xv, j);
            acc = fmaf(xb, gw[(size_t)(h + j) * EE + lane], acc);
        }
    }
    logits[(size_t)t * EE + lane] = acc;
}

// Top-4 + softmax per token (warp per token), scatter into per-expert lists.
__global__ void topk_kernel(const float* __restrict__ logits) {
    int t = blockIdx.x * 8 + threadIdx.y;
    int lane = threadIdx.x;
    float cur = logits[(size_t)t * EE + lane];
    float vals[KT]; int idxs[KT];
    #pragma unroll
    for (int k = 0; k < KT; k++) {
        float bv = cur; int bi = lane;
        #pragma unroll
        for (int off = 16; off; off >>= 1) {
            float ov = __shfl_xor_sync(0xffffffffu, bv, off);
            int   oi = __shfl_xor_sync(0xffffffffu, bi, off);
            if (ov > bv || (ov == bv && oi < bi)) { bv = ov; bi = oi; }
        }
        vals[k] = bv; idxs[k] = bi;
        if (lane == bi) cur = -3.402823466e38f;
    }
    if (lane == 0) {
        float m = vals[0], s = 0.f, e[KT];
        #pragma unroll
        for (int k = 0; k < KT; k++) { e[k] = expf(vals[k] - m); s += e[k]; }
        float inv = 1.f / s;
        #pragma unroll
        for (int k = 0; k < KT; k++) {
            int ex = idxs[k];
            int slot = atomicAdd(&g_cnt[ex], 1);
            g_tok[ex * CAP + slot] = t;
            g_wt[ex * CAP + slot]  = e[k] * inv;
        }
    }
}

// 128x128 tf32 tensor-core GEMM, BK=16, 256 threads (8 warps, 2x4), warp tile 64x32.
// mma.sync.m16n8k8.tf32 with fp32 accumulate. Inputs rounded via cvt.rna at smem store.
// MODE 0: g_h1 = silu(x @ ws1)
// MODE 1: out  = g_h1 @ ws2
// MODE 2: g_act[e] = silu(gather(x) @ w1[e])
// MODE 3: atomicAdd(out[token], w * (g_act[e] @ w2[e]))
template <int MODE>
__global__ __launch_bounds__(256)
void gemm_tf32(const float* __restrict__ Ain, const float* __restrict__ Bin,
               float* __restrict__ Cout, int N, int Kd) {
    int e = 0, rows;
    const float* A = Ain;
    const float* B = Bin;
    const int*   tokl = nullptr;
    const float* wtl  = nullptr;
    if (MODE == 2 || MODE == 3) {
        e = blockIdx.z;
        rows = g_cnt[e];
        if ((int)(blockIdx.y * 128) >= rows) return;   // early-exit empty row tiles
        tokl = g_tok + e * CAP;
        wtl  = g_wt  + e * CAP;
        if (MODE == 2) { B = Bin + (size_t)e * HH * MI; }
        else           { A = g_act + (size_t)e * CAP * MI; B = Bin + (size_t)e * MI * HH; }
    } else {
        rows = TT;
    }
    if (MODE == 1) A = g_h1;

    // [k][m]/[k][n] layout, stride 132 (4-bank skew, float4-aligned)
    __shared__ float As[2][16][132];
    __shared__ float Bs[2][16][132];

    const int tid  = threadIdx.x;
    const int lane = tid & 31, warp = tid >> 5;
    const int gid  = lane >> 2, tig = lane & 3;     // mma group / thread-in-group
    const int wr   = warp >> 2, wc = warp & 3;      // warp 2x4 layout
    const int row0 = blockIdx.y * 128, col0 = blockIdx.x * 128;

    // global->smem mapping: A: 128 rows x 16 k (8 floats/thread), B: 16 k x 128 cols
    const int ar = tid >> 1,  ac   = (tid & 1) * 8;
    const int brow = tid >> 4, bcol = (tid & 15) * 8;

    const float* aPtr;
    if (MODE == 2) {
        int gr = row0 + ar;
        int tokr = (gr < rows) ? tokl[gr] : 0;      // safe fallback row
        aPtr = A + (size_t)tokr * Kd + ac;
    } else {
        aPtr = A + (size_t)(row0 + ar) * Kd + ac;   // MODE3: memory valid up to CAP rows
    }
    const float* bPtr = B + (size_t)brow * N + col0 + bcol;

    float acc[4][4][4];
    #pragma unroll
    for (int mi = 0; mi < 4; mi++)
        #pragma unroll
        for (int ni = 0; ni < 4; ni++)
            #pragma unroll
            for (int c = 0; c < 4; c++) acc[mi][ni][c] = 0.f;

    // tf32-round + store to smem
    auto storeTile = [&](int nb, float4 u, float4 v, float4 p, float4 q) {
        As[nb][ac + 0][ar] = f2tf(u.x); As[nb][ac + 1][ar] = f2tf(u.y);
        As[nb][ac + 2][ar] = f2tf(u.z); As[nb][ac + 3][ar] = f2tf(u.w);
        As[nb][ac + 4][ar] = f2tf(v.x); As[nb][ac + 5][ar] = f2tf(v.y);
        As[nb][ac + 6][ar] = f2tf(v.z); As[nb][ac + 7][ar] = f2tf(v.w);
        float4 t0 = make_float4(f2tf(p.x), f2tf(p.y), f2tf(p.z), f2tf(p.w));
        float4 t1 = make_float4(f2tf(q.x), f2tf(q.y), f2tf(q.z), f2tf(q.w));
        *(float4*)&Bs[nb][brow][bcol]     = t0;
        *(float4*)&Bs[nb][brow][bcol + 4] = t1;
    };

    {
        float4 u = *(const float4*)aPtr;
        float4 v = *(const float4*)(aPtr + 4);
        float4 p = *(const float4*)bPtr;
        float4 q = *(const float4*)(bPtr + 4);
        storeTile(0, u, v, p, q);
    }
    __syncthreads();

    const int nk = Kd / 16;
    int buf = 0;
    for (int kt = 0; kt < nk; kt++) {
        float4 nu, nv, np, nq;
        bool more = (kt + 1 < nk);
        if (more) {
            const float* ap = aPtr + (kt + 1) * 16;
            nu = *(const float4*)ap;
            nv = *(const float4*)(ap + 4);
            const float* bp = bPtr + (size_t)(kt + 1) * 16 * N;
            np = *(const float4*)bp;
            nq = *(const float4*)(bp + 4);
        }
        #pragma unroll
        for (int ks = 0; ks < 16; ks += 8) {
            unsigned af[4][4], bf[4][2];
            #pragma unroll
            for (int mi = 0; mi < 4; mi++) {
                int r = wr * 64 + mi * 16 + gid;
                af[mi][0] = __float_as_uint(As[buf][ks + tig][r]);
                af[mi][1] = __float_as_uint(As[buf][ks + tig][r + 8]);
                af[mi][2] = __float_as_uint(As[buf][ks + tig + 4][r]);
                af[mi][3] = __float_as_uint(As[buf][ks + tig + 4][r + 8]);
            }
            #pragma unroll
            for (int ni = 0; ni < 4; ni++) {
                int c = wc * 32 + ni * 8 + gid;
                bf[ni][0] = __float_as_uint(Bs[buf][ks + tig][c]);
                bf[ni][1] = __float_as_uint(Bs[buf][ks + tig + 4][c]);
            }
            #pragma unroll
            for (int mi = 0; mi < 4; mi++)
                #pragma unroll
                for (int ni = 0; ni < 4; ni++)
                    asm volatile(
                        "mma.sync.aligned.m16n8k8.row.col.f32.tf32.tf32.f32 "
                        "{%0,%1,%2,%3}, {%4,%5,%6,%7}, {%8,%9}, {%0,%1,%2,%3};"
                        : "+f"(acc[mi][ni][0]), "+f"(acc[mi][ni][1]),
                          "+f"(acc[mi][ni][2]), "+f"(acc[mi][ni][3])
                        : "r"(af[mi][0]), "r"(af[mi][1]), "r"(af[mi][2]), "r"(af[mi][3]),
                          "r"(bf[ni][0]), "r"(bf[ni][1]));
        }
        if (more) {
            storeTile(buf ^ 1, nu, nv, np, nq);
            __syncthreads();
            buf ^= 1;
        }
    }

    // Epilogue
    #pragma unroll
    for (int mi = 0; mi < 4; mi++) {
        #pragma unroll
        for (int half = 0; half < 2; half++) {
            int r = row0 + wr * 64 + mi * 16 + gid + half * 8;
            if ((MODE == 2 || MODE == 3) && r >= rows) continue;
            #pragma unroll
            for (int ni = 0; ni < 4; ni++) {
                int c = col0 + wc * 32 + ni * 8 + tig * 2;
                float v0 = acc[mi][ni][half * 2 + 0];
                float v1 = acc[mi][ni][half * 2 + 1];
                if (MODE == 0) {
                    float2* p = (float2*)(g_h1 + (size_t)r * II + c);
                    *p = make_float2(silu_f(v0), silu_f(v1));
                } else if (MODE == 1) {
                    float2* p = (float2*)(Cout + (size_t)r * HH + c);
                    *p = make_float2(v0, v1);
                } else if (MODE == 2) {
                    float2* p = (float2*)(g_act + ((size_t)e * CAP + r) * MI + c);
                    *p = make_float2(silu_f(v0), silu_f(v1));
                } else {
                    int tokn = tokl[r];
                    float w  = wtl[r];
                    float* p = Cout + (size_t)tokn * HH + c;
                    atomicAdd(&p[0], v0 * w);
                    atomicAdd(&p[1], v1 * w);
                }
            }
        }
    }
}

extern "C" void kernel_launch(void* const* d_in, const int* in_sizes, int n_in,
                              void* d_out, int out_size) {
    (void)in_sizes; (void)n_in; (void)out_size;
    const float* x   = (const float*)d_in[0];   // [T, H]
    const float* gw  = (const float*)d_in[1];   // [H, E]
    const float* w1  = (const float*)d_in[2];   // [E, H, M]
    const float* w2  = (const float*)d_in[3];   // [E, M, H]
    const float* ws1 = (const float*)d_in[4];   // [H, I]
    const float* ws2 = (const float*)d_in[5];   // [I, H]
    float* out    = (float*)d_out;              // [T, H] then [T, E] logits
    float* logits = out + (size_t)TT * HH;

    reset_kernel<<<1, 32>>>();
    router_kernel<<<TT / 8, dim3(32, 8)>>>(x, gw, logits);
    topk_kernel<<<TT / 8, dim3(32, 8)>>>(logits);

    // expert up: silu(gather(x) @ w1[e]) -> g_act
    gemm_tf32<2><<<dim3(MI / 128, CAP / 128, EE), 256>>>(x, w1, nullptr, MI, HH);
    // shared expert: h1 = silu(x @ ws1); out = h1 @ ws2 (plain store initializes out)
    gemm_tf32<0><<<dim3(II / 128, TT / 128), 256>>>(x, ws1, nullptr, II, HH);
    gemm_tf32<1><<<dim3(HH / 128, TT / 128), 256>>>(nullptr, ws2, out, HH, II);
    // expert down: out += w * (g_act[e] @ w2[e])
    gemm_tf32<3><<<dim3(HH / 128, CAP / 128, EE), 256>>>(nullptr, w2, out, HH, MI);
}

// round 6
// speedup vs baseline: 2.1321x; 1.0166x over previous
#include <cuda_runtime.h>
#include <math.h>

// Problem constants
constexpr int TT  = 2048;   // tokens = B*S
constexpr int HH  = 2048;   // hidden
constexpr int II  = 8192;   // shared intermediate
constexpr int EE  = 32;     // experts
constexpr int KT  = 4;      // top-k
constexpr int MI  = 1408;   // moe intermediate
constexpr int CAP = 2048;   // per-expert token capacity (worst case)

// Scratch (device globals: allocation-free per harness rules)
__device__ float g_h1[(size_t)TT * II];            // shared-expert hidden (silu'ed)
__device__ float g_act[(size_t)EE * CAP * MI];     // expert up activations (silu'ed)
__device__ int   g_cnt[EE];
__device__ int   g_tok[EE * CAP];
__device__ float g_wt[EE * CAP];

__device__ __forceinline__ float silu_f(float v) { return v / (1.0f + expf(-v)); }
__device__ __forceinline__ float f2tf(float v) {
    unsigned r;
    asm("cvt.rna.tf32.f32 %0, %1;" : "=r"(r) : "f"(v));
    return __uint_as_float(r);
}

__global__ void reset_kernel() {
    if (threadIdx.x < EE) g_cnt[threadIdx.x] = 0;
}

// Router logits: one warp per token, lane = expert column. Exact fp32 (part of output).
__global__ void router_kernel(const float* __restrict__ x, const float* __restrict__ gw,
                              float* __restrict__ logits) {
    int t = blockIdx.x * 8 + threadIdx.y;
    int lane = threadIdx.x;
    const float* xr = x + (size_t)t * HH;
    float acc = 0.f;
    for (int h = 0; h < HH; h += 32) {
        float xv = xr[h + lane];
        #pragma unroll
        for (int j = 0; j < 32; j++) {
            float xb = __shfl_sync(0xffffffffu, xv, j);
            acc = fmaf(xb, gw[(size_t)(h + j) * EE + lane], acc);
        }
    }
    logits[(size_t)t * EE + lane] = acc;
}

// Top-4 + softmax per token (warp per token), scatter into per-expert lists.
__global__ void topk_kernel(const float* __restrict__ logits) {
    int t = blockIdx.x * 8 + threadIdx.y;
    int lane = threadIdx.x;
    float cur = logits[(size_t)t * EE + lane];
    float vals[KT]; int idxs[KT];
    #pragma unroll
    for (int k = 0; k < KT; k++) {
        float bv = cur; int bi = lane;
        #pragma unroll
        for (int off = 16; off; off >>= 1) {
            float ov = __shfl_xor_sync(0xffffffffu, bv, off);
            int   oi = __shfl_xor_sync(0xffffffffu, bi, off);
            if (ov > bv || (ov == bv && oi < bi)) { bv = ov; bi = oi; }
        }
        vals[k] = bv; idxs[k] = bi;
        if (lane == bi) cur = -3.402823466e38f;
    }
    if (lane == 0) {
        float m = vals[0], s = 0.f, e[KT];
        #pragma unroll
        for (int k = 0; k < KT; k++) { e[k] = expf(vals[k] - m); s += e[k]; }
        float inv = 1.f / s;
        #pragma unroll
        for (int k = 0; k < KT; k++) {
            int ex = idxs[k];
            int slot = atomicAdd(&g_cnt[ex], 1);
            g_tok[ex * CAP + slot] = t;
            g_wt[ex * CAP + slot]  = e[k] * inv;
        }
    }
}

// 128x128 tf32 tensor-core GEMM, BK=16, 256 threads (8 warps, 2x4), warp tile 64x32.
// Smem stride 136 (== 8 mod 32): fragment-load bank = (8*tig+gid)%32, a bijection
// over the warp -> zero bank conflicts. A-store mapping ar=tid&127 -> conflict-free.
// MODE 0: g_h1 = silu(x @ ws1)
// MODE 1: out  = g_h1 @ ws2
// MODE 2: g_act[e] = silu(gather(x) @ w1[e])
// MODE 3: atomicAdd(out[token], w * (g_act[e] @ w2[e]))
template <int MODE>
__global__ __launch_bounds__(256)
void gemm_tf32(const float* __restrict__ Ain, const float* __restrict__ Bin,
               float* __restrict__ Cout, int N, int Kd) {
    int e = 0, rows;
    const float* A = Ain;
    const float* B = Bin;
    const int*   tokl = nullptr;
    const float* wtl  = nullptr;
    if (MODE == 2 || MODE == 3) {
        e = blockIdx.z;
        rows = g_cnt[e];
        if ((int)(blockIdx.y * 128) >= rows) return;   // early-exit empty row tiles
        tokl = g_tok + e * CAP;
        wtl  = g_wt  + e * CAP;
        if (MODE == 2) { B = Bin + (size_t)e * HH * MI; }
        else           { A = g_act + (size_t)e * CAP * MI; B = Bin + (size_t)e * MI * HH; }
    } else {
        rows = TT;
    }
    if (MODE == 1) A = g_h1;

    // [k][m]/[k][n] layout, stride 136 (8 mod 32 -> conflict-free fragment loads)
    __shared__ float As[2][16][136];
    __shared__ float Bs[2][16][136];

    const int tid  = threadIdx.x;
    const int lane = tid & 31, warp = tid >> 5;
    const int gid  = lane >> 2, tig = lane & 3;     // mma group / thread-in-group
    const int wr   = warp >> 2, wc = warp & 3;      // warp 2x4 layout
    const int row0 = blockIdx.y * 128, col0 = blockIdx.x * 128;

    // global->smem mapping:
    // A: thread covers row (tid&127), k-chunk (tid>>7)*8 .. +7  (conflict-free STS)
    // B: 16 k x 128 cols, float4 x2 per thread
    const int ar = tid & 127, ac = (tid >> 7) * 8;
    const int brow = tid >> 4, bcol = (tid & 15) * 8;

    const float* aPtr;
    if (MODE == 2) {
        int gr = row0 + ar;
        int tokr = (gr < rows) ? tokl[gr] : 0;      // safe fallback row
        aPtr = A + (size_t)tokr * Kd + ac;
    } else {
        aPtr = A + (size_t)(row0 + ar) * Kd + ac;   // MODE3: memory valid up to CAP rows
    }
    const float* bPtr = B + (size_t)brow * N + col0 + bcol;

    float acc[4][4][4];
    #pragma unroll
    for (int mi = 0; mi < 4; mi++)
        #pragma unroll
        for (int ni = 0; ni < 4; ni++)
            #pragma unroll
            for (int c = 0; c < 4; c++) acc[mi][ni][c] = 0.f;

    // tf32-round + store to smem
    auto storeTile = [&](int nb, float4 u, float4 v, float4 p, float4 q) {
        As[nb][ac + 0][ar] = f2tf(u.x); As[nb][ac + 1][ar] = f2tf(u.y);
        As[nb][ac + 2][ar] = f2tf(u.z); As[nb][ac + 3][ar] = f2tf(u.w);
        As[nb][ac + 4][ar] = f2tf(v.x); As[nb][ac + 5][ar] = f2tf(v.y);
        As[nb][ac + 6][ar] = f2tf(v.z); As[nb][ac + 7][ar] = f2tf(v.w);
        float4 t0 = make_float4(f2tf(p.x), f2tf(p.y), f2tf(p.z), f2tf(p.w));
        float4 t1 = make_float4(f2tf(q.x), f2tf(q.y), f2tf(q.z), f2tf(q.w));
        *(float4*)&Bs[nb][brow][bcol]     = t0;
        *(float4*)&Bs[nb][brow][bcol + 4] = t1;
    };

    {
        float4 u = *(const float4*)aPtr;
        float4 v = *(const float4*)(aPtr + 4);
        float4 p = *(const float4*)bPtr;
        float4 q = *(const float4*)(bPtr + 4);
        storeTile(0, u, v, p, q);
    }
    __syncthreads();

    const int nk = Kd / 16;
    int buf = 0;
    for (int kt = 0; kt < nk; kt++) {
        float4 nu, nv, np, nq;
        bool more = (kt + 1 < nk);
        if (more) {
            const float* ap = aPtr + (kt + 1) * 16;
            nu = *(const float4*)ap;
            nv = *(const float4*)(ap + 4);
            const float* bp = bPtr + (size_t)(kt + 1) * 16 * N;
            np = *(const float4*)bp;
            nq = *(const float4*)(bp + 4);
        }
        #pragma unroll
        for (int ks = 0; ks < 16; ks += 8) {
            unsigned af[4][4], bf[4][2];
            #pragma unroll
            for (int mi = 0; mi < 4; mi++) {
                int r = wr * 64 + mi * 16 + gid;
                af[mi][0] = __float_as_uint(As[buf][ks + tig][r]);
                af[mi][1] = __float_as_uint(As[buf][ks + tig][r + 8]);
                af[mi][2] = __float_as_uint(As[buf][ks + tig + 4][r]);
                af[mi][3] = __float_as_uint(As[buf][ks + tig + 4][r + 8]);
            }
            #pragma unroll
            for (int ni = 0; ni < 4; ni++) {
                int c = wc * 32 + ni * 8 + gid;
                bf[ni][0] = __float_as_uint(Bs[buf][ks + tig][c]);
                bf[ni][1] = __float_as_uint(Bs[buf][ks + tig + 4][c]);
            }
            #pragma unroll
            for (int mi = 0; mi < 4; mi++)
                #pragma unroll
                for (int ni = 0; ni < 4; ni++)
                    asm volatile(
                        "mma.sync.aligned.m16n8k8.row.col.f32.tf32.tf32.f32 "
                        "{%0,%1,%2,%3}, {%4,%5,%6,%7}, {%8,%9}, {%0,%1,%2,%3};"
                        : "+f"(acc[mi][ni][0]), "+f"(acc[mi][ni][1]),
                          "+f"(acc[mi][ni][2]), "+f"(acc[mi][ni][3])
                        : "r"(af[mi][0]), "r"(af[mi][1]), "r"(af[mi][2]), "r"(af[mi][3]),
                          "r"(bf[ni][0]), "r"(bf[ni][1]));
        }
        if (more) {
            storeTile(buf ^ 1, nu, nv, np, nq);
            __syncthreads();
            buf ^= 1;
        }
    }

    // Epilogue
    #pragma unroll
    for (int mi = 0; mi < 4; mi++) {
        #pragma unroll
        for (int half = 0; half < 2; half++) {
            int r = row0 + wr * 64 + mi * 16 + gid + half * 8;
            if ((MODE == 2 || MODE == 3) && r >= rows) continue;
            #pragma unroll
            for (int ni = 0; ni < 4; ni++) {
                int c = col0 + wc * 32 + ni * 8 + tig * 2;
                float v0 = acc[mi][ni][half * 2 + 0];
                float v1 = acc[mi][ni][half * 2 + 1];
                if (MODE == 0) {
                    float2* p = (float2*)(g_h1 + (size_t)r * II + c);
                    *p = make_float2(silu_f(v0), silu_f(v1));
                } else if (MODE == 1) {
                    float2* p = (float2*)(Cout + (size_t)r * HH + c);
                    *p = make_float2(v0, v1);
                } else if (MODE == 2) {
                    float2* p = (float2*)(g_act + ((size_t)e * CAP + r) * MI + c);
                    *p = make_float2(silu_f(v0), silu_f(v1));
                } else {
                    int tokn = tokl[r];
                    float w  = wtl[r];
                    float* p = Cout + (size_t)tokn * HH + c;
                    atomicAdd(&p[0], v0 * w);
                    atomicAdd(&p[1], v1 * w);
                }
            }
        }
    }
}

extern "C" void kernel_launch(void* const* d_in, const int* in_sizes, int n_in,
                              void* d_out, int out_size) {
    (void)in_sizes; (void)n_in; (void)out_size;
    const float* x   = (const float*)d_in[0];   // [T, H]
    const float* gw  = (const float*)d_in[1];   // [H, E]
    const float* w1  = (const float*)d_in[2];   // [E, H, M]
    const float* w2  = (const float*)d_in[3];   // [E, M, H]
    const float* ws1 = (const float*)d_in[4];   // [H, I]
    const float* ws2 = (const float*)d_in[5];   // [I, H]
    float* out    = (float*)d_out;              // [T, H] then [T, E] logits
    float* logits = out + (size_t)TT * HH;

    reset_kernel<<<1, 32>>>();
    router_kernel<<<TT / 8, dim3(32, 8)>>>(x, gw, logits);
    topk_kernel<<<TT / 8, dim3(32, 8)>>>(logits);

    // expert up: silu(gather(x) @ w1[e]) -> g_act
    gemm_tf32<2><<<dim3(MI / 128, CAP / 128, EE), 256>>>(x, w1, nullptr, MI, HH);
    // shared expert: h1 = silu(x @ ws1); out = h1 @ ws2 (plain store initializes out)
    gemm_tf32<0><<<dim3(II / 128, TT / 128), 256>>>(x, ws1, nullptr, II, HH);
    gemm_tf32<1><<<dim3(HH / 128, TT / 128), 256>>>(nullptr, ws2, out, HH, II);
    // expert down: out += w * (g_act[e] @ w2[e])
    gemm_tf32<3><<<dim3(HH / 128, CAP / 128, EE), 256>>>(nullptr, w2, out, HH, MI);
}

// round 9
// speedup vs baseline: 2.4456x; 1.1470x over previous
#include <cuda_runtime.h>
#include <math.h>
#include <stdint.h>

// Problem constants
constexpr int TT  = 2048;
constexpr int HH  = 2048;
constexpr int II  = 8192;
constexpr int EE  = 32;
constexpr int KT  = 4;
constexpr int MI  = 1408;
constexpr int CAP = 2048;

// Scratch (device globals)
__device__ float g_h1[(size_t)TT * II];
__device__ float g_act[(size_t)EE * CAP * MI];
__device__ int   g_cnt[EE];
__device__ int   g_tok[EE * CAP];
__device__ float g_wt[EE * CAP];

__device__ __forceinline__ float silu_f(float v) { return v / (1.0f + expf(-v)); }
__device__ __forceinline__ unsigned f2tf_u(float v) {
    unsigned r;
    asm("cvt.rna.tf32.f32 %0, %1;" : "=r"(r) : "f"(v));
    return r;
}
__device__ __forceinline__ uint32_t smem_u32(const void* p) {
    uint32_t a;
    asm("{ .reg .u64 t; cvta.to.shared.u64 t, %1; cvt.u32.u64 %0, t; }" : "=r"(a) : "l"(p));
    return a;
}
__device__ __forceinline__ void cpasync16(uint32_t dst, const void* src) {
    asm volatile("cp.async.cg.shared.global [%0], [%1], 16;" :: "r"(dst), "l"(src) : "memory");
}
#define CP_COMMIT() asm volatile("cp.async.commit_group;" ::: "memory")
#define CP_WAIT1()  asm volatile("cp.async.wait_group 1;" ::: "memory")
#define CP_WAIT0()  asm volatile("cp.async.wait_group 0;" ::: "memory")

__global__ void reset_kernel() {
    if (threadIdx.x < EE) g_cnt[threadIdx.x] = 0;
}

__global__ void router_kernel(const float* __restrict__ x, const float* __restrict__ gw,
                              float* __restrict__ logits) {
    int t = blockIdx.x * 8 + threadIdx.y;
    int lane = threadIdx.x;
    const float* xr = x + (size_t)t * HH;
    float acc = 0.f;
    for (int h = 0; h < HH; h += 32) {
        float xv = xr[h + lane];
        #pragma unroll
        for (int j = 0; j < 32; j++) {
            float xb = __shfl_sync(0xffffffffu, xv, j);
            acc = fmaf(xb, gw[(size_t)(h + j) * EE + lane], acc);
        }
    }
    logits[(size_t)t * EE + lane] = acc;
}

__global__ void topk_kernel(const float* __restrict__ logits) {
    int t = blockIdx.x * 8 + threadIdx.y;
    int lane = threadIdx.x;
    float cur = logits[(size_t)t * EE + lane];
    float vals[KT]; int idxs[KT];
    #pragma unroll
    for (int k = 0; k < KT; k++) {
        float bv = cur; int bi = lane;
        #pragma unroll
        for (int off = 16; off; off >>= 1) {
            float ov = __shfl_xor_sync(0xffffffffu, bv, off);
            int   oi = __shfl_xor_sync(0xffffffffu, bi, off);
            if (ov > bv || (ov == bv && oi < bi)) { bv = ov; bi = oi; }
        }
        vals[k] = bv; idxs[k] = bi;
        if (lane == bi) cur = -3.402823466e38f;
    }
    if (lane == 0) {
        float m = vals[0], s = 0.f, e[KT];
        #pragma unroll
        for (int k = 0; k < KT; k++) { e[k] = expf(vals[k] - m); s += e[k]; }
        float inv = 1.f / s;
        #pragma unroll
        for (int k = 0; k < KT; k++) {
            int ex = idxs[k];
            int slot = atomicAdd(&g_cnt[ex], 1);
            g_tok[ex * CAP + slot] = t;
            g_wt[ex * CAP + slot]  = e[k] * inv;
        }
    }
}

// ── tf32 mma.sync GEMM: CTA 128x128, 128 threads = 4 warps (2x2), warp tile 64x64.
// cp.async 3-stage pipeline, BK=16.
// A smem: [m][k] stride 20 floats (bank-bijective loads, 16B-aligned cp.async rows).
// B smem: [k][n] stride 136 floats (conflict-free, 16B-aligned).
// tf32 cvt.rna applied at fragment-load time (fma pipe is idle).
// MODE 0: g_h1 = silu(x @ ws1)   MODE 1: out = g_h1 @ ws2
// MODE 2: g_act[e] = silu(gather(x) @ w1[e])
// MODE 3: atomicAdd(out[token], w * (g_act[e] @ w2[e]))
constexpr int BM = 128, BN = 128, BK = 16;
constexpr int PAD_A = 20;                       // floats per A row
constexpr int STR_B = 136;                      // floats per B k-row
constexpr int A_BYTES = BM * PAD_A * 4;         // 10240
constexpr int B_BYTES = BK * STR_B * 4;         // 8704
constexpr int STAGE_BYTES = A_BYTES + B_BYTES;  // 18944
constexpr int NSTAGE = 3;
constexpr int SMEM_TOTAL = NSTAGE * STAGE_BYTES; // 56832

template <int MODE>
__global__ __launch_bounds__(128)
void gemm_tf32(const float* __restrict__ Ain, const float* __restrict__ Bin,
               float* __restrict__ Cout, int N, int Kd) {
    extern __shared__ char smem[];
    int e = 0, rows;
    const float* A = Ain;
    const float* B = Bin;
    const int*   tokl = nullptr;
    const float* wtl  = nullptr;
    const int row0 = blockIdx.y * BM, col0 = blockIdx.x * BN;
    if (MODE == 2 || MODE == 3) {
        e = blockIdx.z;
        rows = g_cnt[e];
        if (row0 >= rows) return;
        tokl = g_tok + e * CAP;
        wtl  = g_wt  + e * CAP;
        if (MODE == 2) { B = Bin + (size_t)e * HH * MI; }
        else           { A = g_act + (size_t)e * CAP * MI; B = Bin + (size_t)e * MI * HH; }
    } else {
        rows = TT;
    }
    if (MODE == 1) A = g_h1;

    const uint32_t sb = smem_u32(smem);
    const int tid = threadIdx.x;
    const int lane = tid & 31, warp = tid >> 5;
    const int gid = lane >> 2, tig = lane & 3;
    const int wr = warp >> 1, wc = warp & 1;

    // Fill mappings
    // A: thread = one m-row (tid), 4x 16B along k
    const float* aRow;
    if (MODE == 2) {
        int gr = row0 + tid;
        int tok = (gr < rows) ? tokl[gr] : 0;
        aRow = A + (size_t)tok * Kd;
    } else {
        aRow = A + (size_t)(row0 + tid) * Kd;   // MODE3: memory valid up to CAP rows
    }
    // B: thread covers k-row (tid>>3), 4 chunks of 16B across n
    const int bk = tid >> 3, bc8 = tid & 7;
    const float* bRow = B + (size_t)bk * N + col0;

    auto fill = [&](int st, int k0) {
        uint32_t abase = sb + st * STAGE_BYTES;
        uint32_t bbase = abase + A_BYTES;
        uint32_t adst = abase + (uint32_t)tid * (PAD_A * 4);
        #pragma unroll
        for (int j = 0; j < 4; j++)
            cpasync16(adst + j * 16, aRow + k0 + j * 4);
        const float* bsrc = bRow + (size_t)k0 * N;
        uint32_t bdst = bbase + (uint32_t)bk * (STR_B * 4);
        #pragma unroll
        for (int j = 0; j < 4; j++) {
            int n = (bc8 + j * 8) * 4;
            cpasync16(bdst + n * 4, bsrc + n);
        }
    };

    float acc[4][8][4];
    #pragma unroll
    for (int mi = 0; mi < 4; mi++)
        #pragma unroll
        for (int ni = 0; ni < 8; ni++)
            #pragma unroll
            for (int c = 0; c < 4; c++) acc[mi][ni][c] = 0.f;

    const int nk = Kd / BK;
    fill(0, 0);  CP_COMMIT();
    fill(1, BK); CP_COMMIT();

    for (int kc = 0; kc < nk; kc++) {
        if (kc + 1 == nk) { CP_WAIT0(); } else { CP_WAIT1(); }
        __syncthreads();
        if (kc + 2 < nk) { fill((kc + 2) % NSTAGE, (kc + 2) * BK); CP_COMMIT(); }

        int st = kc % NSTAGE;
        const float* Am = (const float*)(smem + st * STAGE_BYTES);
        const float* Bk = (const float*)(smem + st * STAGE_BYTES + A_BYTES);

        #pragma unroll
        for (int ks = 0; ks < BK; ks += 8) {
            unsigned af[4][4], bf[8][2];
            #pragma unroll
            for (int mi = 0; mi < 4; mi++) {
                int r = wr * 64 + mi * 16 + gid;
                af[mi][0] = f2tf_u(Am[(r    ) * PAD_A + ks + tig    ]);
                af[mi][1] = f2tf_u(Am[(r + 8) * PAD_A + ks + tig    ]);
                af[mi][2] = f2tf_u(Am[(r    ) * PAD_A + ks + tig + 4]);
                af[mi][3] = f2tf_u(Am[(r + 8) * PAD_A + ks + tig + 4]);
            }
            #pragma unroll
            for (int ni = 0; ni < 8; ni++) {
                int c = wc * 64 + ni * 8 + gid;
                bf[ni][0] = f2tf_u(Bk[(ks + tig    ) * STR_B + c]);
                bf[ni][1] = f2tf_u(Bk[(ks + tig + 4) * STR_B + c]);
            }
            #pragma unroll
            for (int mi = 0; mi < 4; mi++)
                #pragma unroll
                for (int ni = 0; ni < 8; ni++)
                    asm volatile(
                        "mma.sync.aligned.m16n8k8.row.col.f32.tf32.tf32.f32 "
                        "{%0,%1,%2,%3}, {%4,%5,%6,%7}, {%8,%9}, {%0,%1,%2,%3};"
                        : "+f"(acc[mi][ni][0]), "+f"(acc[mi][ni][1]),
                          "+f"(acc[mi][ni][2]), "+f"(acc[mi][ni][3])
                        : "r"(af[mi][0]), "r"(af[mi][1]), "r"(af[mi][2]), "r"(af[mi][3]),
                          "r"(bf[ni][0]), "r"(bf[ni][1]));
        }
    }

    // Epilogue: direct float2 stores per fragment
    #pragma unroll
    for (int mi = 0; mi < 4; mi++) {
        #pragma unroll
        for (int half = 0; half < 2; half++) {
            int r = row0 + wr * 64 + mi * 16 + gid + half * 8;
            if ((MODE == 2 || MODE == 3) && r >= rows) continue;
            #pragma unroll
            for (int ni = 0; ni < 8; ni++) {
                int c = col0 + wc * 64 + ni * 8 + tig * 2;
                float v0 = acc[mi][ni][half * 2 + 0];
                float v1 = acc[mi][ni][half * 2 + 1];
                if (MODE == 0) {
                    float2* p = (float2*)(g_h1 + (size_t)r * II + c);
                    *p = make_float2(silu_f(v0), silu_f(v1));
                } else if (MODE == 1) {
                    float2* p = (float2*)(Cout + (size_t)r * HH + c);
                    *p = make_float2(v0, v1);
                } else if (MODE == 2) {
                    float2* p = (float2*)(g_act + ((size_t)e * CAP + r) * MI + c);
                    *p = make_float2(silu_f(v0), silu_f(v1));
                } else {
                    int tokn = tokl[r];
                    float w  = wtl[r];
                    float* p = Cout + (size_t)tokn * HH + c;
                    atomicAdd(&p[0], v0 * w);
                    atomicAdd(&p[1], v1 * w);
                }
            }
        }
    }
}

extern "C" void kernel_launch(void* const* d_in, const int* in_sizes, int n_in,
                              void* d_out, int out_size) {
    (void)in_sizes; (void)n_in; (void)out_size;
    const float* x   = (const float*)d_in[0];
    const float* gw  = (const float*)d_in[1];
    const float* w1  = (const float*)d_in[2];
    const float* w2  = (const float*)d_in[3];
    const float* ws1 = (const float*)d_in[4];
    const float* ws2 = (const float*)d_in[5];
    float* out    = (float*)d_out;
    float* logits = out + (size_t)TT * HH;

    cudaFuncSetAttribute(gemm_tf32<0>, cudaFuncAttributeMaxDynamicSharedMemorySize, SMEM_TOTAL);
    cudaFuncSetAttribute(gemm_tf32<1>, cudaFuncAttributeMaxDynamicSharedMemorySize, SMEM_TOTAL);
    cudaFuncSetAttribute(gemm_tf32<2>, cudaFuncAttributeMaxDynamicSharedMemorySize, SMEM_TOTAL);
    cudaFuncSetAttribute(gemm_tf32<3>, cudaFuncAttributeMaxDynamicSharedMemorySize, SMEM_TOTAL);

    reset_kernel<<<1, 32>>>();
    router_kernel<<<TT / 8, dim3(32, 8)>>>(x, gw, logits);
    topk_kernel<<<TT / 8, dim3(32, 8)>>>(logits);

    gemm_tf32<2><<<dim3(MI / 128, CAP / 128, EE), 128, SMEM_TOTAL>>>(x, w1, nullptr, MI, HH);
    gemm_tf32<0><<<dim3(II / 128, TT / 128), 128, SMEM_TOTAL>>>(x, ws1, nullptr, II, HH);
    gemm_tf32<1><<<dim3(HH / 128, TT / 128), 128, SMEM_TOTAL>>>(nullptr, ws2, out, HH, II);
    gemm_tf32<3><<<dim3(HH / 128, CAP / 128, EE), 128, SMEM_TOTAL>>>(nullptr, w2, out, HH, MI);
}